// round 15
// baseline (speedup 1.0000x reference)
#include <cuda_runtime.h>
#include <cstdint>

#define N_ENT   100000
#define D       128
#define NB_SCAN 49
#define AS      66                         // EVEN: keeps 8B row-pair LDS aligned
#define GSMEM   (131072 + 128 * AS * 4)    // W-dup 128KB + A ~33.8KB

// ---------------- scratch (static, no allocs) ----------------
__device__ float4 g_neigh4[(size_t)N_ENT * 32];
__device__ float2 g_Wdup[2 * 128 * 128];  // [slab][k][c] = (W[c][k], W[c][k])
__device__ int    g_cnt[N_ENT];
__device__ int    g_start[N_ENT + 1];
__device__ int    g_head[N_ENT];
__device__ int    g_bsum[64];
__device__ float2 g_edge[1600000];

// ---------------- f32x2 helpers ----------------
__device__ __forceinline__ unsigned long long ffma2(unsigned long long a,
                                                    unsigned long long b,
                                                    unsigned long long c) {
    unsigned long long d;
    asm("fma.rn.f32x2 %0, %1, %2, %3;" : "=l"(d) : "l"(a), "l"(b), "l"(c));
    return d;
}
__device__ __forceinline__ void unpack2(unsigned long long v, float& x, float& y) {
    asm("mov.b64 {%0, %1}, %2;" : "=f"(x), "=f"(y) : "l"(v));
}

// ---------------- prep: zero cnt + dup-pair weights (fused) ----------------
__global__ void k_prep(const float* __restrict__ Ws, const float* __restrict__ Wn, int n) {
    int i = blockIdx.x * blockDim.x + threadIdx.x;
    if (i < n) g_cnt[i] = 0;
    if (i < 2 * 128 * 128) {
        int slab = i >> 14, rem = i & 16383, k = rem >> 7, c = rem & 127;
        float w = (slab ? Wn : Ws)[c * 128 + k];
        g_Wdup[i] = make_float2(w, w);
    }
}

// ---------------- CSR build (r13, unchanged) ----------------
__global__ void k_hist(const int* __restrict__ rows, int E) {
    int i = (blockIdx.x * blockDim.x + threadIdx.x) * 4;
    if (i + 4 <= E) {
        int4 r = *(const int4*)(rows + i);
        atomicAdd(&g_cnt[r.x], 1);
        atomicAdd(&g_cnt[r.y], 1);
        atomicAdd(&g_cnt[r.z], 1);
        atomicAdd(&g_cnt[r.w], 1);
    } else {
        for (; i < E; i++) atomicAdd(&g_cnt[rows[i]], 1);
    }
}
__global__ void k_scan1(int n) {
    __shared__ int ss[256];
    int b = blockIdx.x, t = threadIdx.x;
    int base = b * 2048 + t * 8;
    int loc[8], s = 0;
#pragma unroll
    for (int i = 0; i < 8; i++) {
        int idx = base + i;
        loc[i] = (idx < n) ? g_cnt[idx] : 0;
        s += loc[i];
    }
    ss[t] = s;
    __syncthreads();
    for (int off = 1; off < 256; off <<= 1) {
        int v = 0;
        if (t >= off) v = ss[t - off];
        __syncthreads();
        if (t >= off) ss[t] += v;
        __syncthreads();
    }
    int excl = ss[t] - s;
#pragma unroll
    for (int i = 0; i < 8; i++) {
        int idx = base + i;
        if (idx < n) g_start[idx] = excl;
        excl += loc[i];
    }
    if (t == 255) g_bsum[b] = ss[255];
}
__global__ void k_scan3(int n, int E) {
    __shared__ int soff;
    int bb = blockIdx.x >> 3;
    if (threadIdx.x < 32) {
        int s = 0;
        for (int i = threadIdx.x; i < bb; i += 32) s += g_bsum[i];
#pragma unroll
        for (int o = 16; o; o >>= 1) s += __shfl_down_sync(0xFFFFFFFFu, s, o);
        if (threadIdx.x == 0) soff = s;
    }
    __syncthreads();
    int i = blockIdx.x * 256 + threadIdx.x;
    if (i < n) {
        int v = g_start[i] + soff;
        g_start[i] = v;
        g_head[i] = v;
    }
    if (i == 0) g_start[n] = E;
}
__global__ void k_scatter(const int* __restrict__ rows, const int* __restrict__ cols,
                          const float* __restrict__ vals, int E) {
    int i = (blockIdx.x * blockDim.x + threadIdx.x) * 4;
    if (i + 4 <= E) {
        int4 r = *(const int4*)(rows + i);
        int4 c = *(const int4*)(cols + i);
        float4 v = *(const float4*)(vals + i);
        int p0 = atomicAdd(&g_head[r.x], 1);
        int p1 = atomicAdd(&g_head[r.y], 1);
        int p2 = atomicAdd(&g_head[r.z], 1);
        int p3 = atomicAdd(&g_head[r.w], 1);
        g_edge[p0] = make_float2(__int_as_float(c.x), v.x);
        g_edge[p1] = make_float2(__int_as_float(c.y), v.y);
        g_edge[p2] = make_float2(__int_as_float(c.z), v.z);
        g_edge[p3] = make_float2(__int_as_float(c.w), v.w);
    } else {
        for (; i < E; i++) {
            int pos = atomicAdd(&g_head[rows[i]], 1);
            g_edge[pos] = make_float2(__int_as_float(cols[i]), vals[i]);
        }
    }
}
__global__ void k_spmm(const float4* __restrict__ embs, int n) {
    int w = (int)((blockIdx.x * blockDim.x + threadIdx.x) >> 5);
    int lane = threadIdx.x & 31;
    if (w >= n) return;
    int s = g_start[w], t = g_start[w + 1];
    float4 acc = make_float4(0.f, 0.f, 0.f, 0.f);
    int e = s;
    for (; e + 8 <= t; e += 8) {
        float2 ed[8];
        float4 rr[8];
#pragma unroll
        for (int q = 0; q < 8; q++) ed[q] = g_edge[e + q];
#pragma unroll
        for (int q = 0; q < 8; q++)
            rr[q] = embs[(size_t)__float_as_int(ed[q].x) * 32 + lane];
#pragma unroll
        for (int q = 0; q < 8; q++) {
            acc.x += ed[q].y * rr[q].x;
            acc.y += ed[q].y * rr[q].y;
            acc.z += ed[q].y * rr[q].z;
            acc.w += ed[q].y * rr[q].w;
        }
    }
    for (; e < t; e++) {
        float2 ed = g_edge[e];
        float4 r = embs[(size_t)__float_as_int(ed.x) * 32 + lane];
        acc.x += ed.y * r.x; acc.y += ed.y * r.y;
        acc.z += ed.y * r.z; acc.w += ed.y * r.w;
    }
    g_neigh4[(size_t)w * 32 + lane] = acc;
}

// ---------------- GEMM half: row-paired FFMA2 with dup-W (zero pack MOVs) ----------------
// HALF=0: out = x @ Ws^T + (bs + bn)
// HALF=1: out = leaky(out + neigh @ Wn^T)
template <int HALF>
__global__ __launch_bounds__(256)
void k_gemm(const float* __restrict__ A0,
            const float* __restrict__ bs,
            const float* __restrict__ bn,
            float* __restrict__ out, int N) {
    extern __shared__ float sm[];
    char* sW = (char*)sm;           // [128 k][128 c float2 dup] = 1KB/row
    float* sA = sm + 32768;         // [128 k][AS]; reused as red[64][128]
    const float* src = HALF ? (const float*)g_neigh4 : A0;
    int tid = threadIdx.x;
    int tc = tid & 15;              // granule group: granules tc+16j (cols 2g, 2g+1)
    int tr = (tid >> 4) & 7;        // rows tr*8 .. tr*8+7 (4 pairs)
    int kh = tid >> 7;              // split-K half
    int base = blockIdx.x * 64;
    int r0 = tr * 8;

    {   // W: straight 128KB copy of dup slab
        const float4* wt4 = (const float4*)(g_Wdup + HALF * 16384);
        float4* sW4 = (float4*)sW;
#pragma unroll
        for (int i = 0; i < 32; i++) sW4[tid + i * 256] = wt4[tid + i * 256];
    }
    for (int it = 0; it < 32; it++) {
        int r = it * 2 + (tid >> 7);
        int k = tid & 127;
        int gr = base + r;
        float v = (gr < N) ? src[(size_t)gr * 128 + k] : 0.f;
        sA[k * AS + r] = v;
    }
    __syncthreads();

    unsigned long long acc[4][8];
#pragma unroll
    for (int i = 0; i < 4; i++)
#pragma unroll
        for (int j = 0; j < 8; j++) acc[i][j] = 0ull;

    int k0 = kh * 64;
#pragma unroll 4
    for (int kk = 0; kk < 64; kk++) {
        int k = k0 + kk;
        const char* wk = sW + k * 1024 + tc * 16;
        ulonglong2 wq[4];
#pragma unroll
        for (int j = 0; j < 4; j++)
            wq[j] = *(const ulonglong2*)(wk + j * 256);     // granules tc+16j
        const float* ak = sA + k * AS + r0;
        unsigned long long a[4];
#pragma unroll
        for (int i = 0; i < 4; i++)
            a[i] = *(const unsigned long long*)(ak + 2 * i); // aligned row pair (AS even)
#pragma unroll
        for (int i = 0; i < 4; i++)
#pragma unroll
            for (int j = 0; j < 4; j++) {
                acc[i][2 * j]     = ffma2(a[i], wq[j].x, acc[i][2 * j]);
                acc[i][2 * j + 1] = ffma2(a[i], wq[j].y, acc[i][2 * j + 1]);
            }
    }

    __syncthreads();
    float* red = sA;                // [64][128]
    if (kh == 1) {
#pragma unroll
        for (int i = 0; i < 4; i++) {
#pragma unroll
            for (int j = 0; j < 4; j++) {
                int c = 2 * (tc + 16 * j);
                float l0, h0, l1, h1;
                unpack2(acc[i][2 * j], l0, h0);
                unpack2(acc[i][2 * j + 1], l1, h1);
                *(float2*)(red + (r0 + 2 * i) * 128 + c)     = make_float2(l0, l1);
                *(float2*)(red + (r0 + 2 * i + 1) * 128 + c) = make_float2(h0, h1);
            }
        }
    }
    __syncthreads();
    if (kh == 0) {
        float bb[8];
        if (!HALF) {
#pragma unroll
            for (int j = 0; j < 4; j++) {
                int c = 2 * (tc + 16 * j);
                bb[2 * j]     = bs[c] + bn[c];
                bb[2 * j + 1] = bs[c + 1] + bn[c + 1];
            }
        }
#pragma unroll
        for (int i = 0; i < 4; i++) {
            float v[2][8];
#pragma unroll
            for (int j = 0; j < 4; j++) {
                float l0, h0, l1, h1;
                unpack2(acc[i][2 * j], l0, h0);
                unpack2(acc[i][2 * j + 1], l1, h1);
                v[0][2 * j] = l0; v[0][2 * j + 1] = l1;
                v[1][2 * j] = h0; v[1][2 * j + 1] = h1;
            }
#pragma unroll
            for (int s = 0; s < 2; s++) {
                int gr = base + r0 + 2 * i + s;
                if (gr >= N) continue;
                float* op = out + (size_t)gr * 128;
                const float* rp = red + (r0 + 2 * i + s) * 128;
#pragma unroll
                for (int j = 0; j < 4; j++) {
                    int c = 2 * (tc + 16 * j);
                    float t0 = v[s][2 * j]     + rp[c];
                    float t1 = v[s][2 * j + 1] + rp[c + 1];
                    if (HALF) {
                        float2 o = *(const float2*)(op + c);
                        t0 += o.x; t1 += o.y;
                        t0 = t0 > 0.f ? t0 : 0.01f * t0;
                        t1 = t1 > 0.f ? t1 : 0.01f * t1;
                    } else {
                        t0 += bb[2 * j];
                        t1 += bb[2 * j + 1];
                    }
                    *(float2*)(op + c) = make_float2(t0, t1);
                }
            }
        }
    }
}

extern "C" void kernel_launch(void* const* d_in, const int* in_sizes, int n_in,
                              void* d_out, int out_size) {
    const float* embs = (const float*)d_in[0];
    const int*   rows = (const int*)d_in[1];
    const int*   cols = (const int*)d_in[2];
    const float* vals = (const float*)d_in[3];
    const float* Ws   = (const float*)d_in[4];
    const float* bs   = (const float*)d_in[5];
    const float* Wn   = (const float*)d_in[6];
    const float* bn   = (const float*)d_in[7];
    float* out = (float*)d_out;

    int N = in_sizes[0] / D;
    int E = in_sizes[1];

    static cudaStream_t s2 = nullptr;
    static cudaEvent_t evA = nullptr, evB = nullptr;
    if (!s2) {
        cudaStreamCreateWithFlags(&s2, cudaStreamNonBlocking);
        cudaEventCreateWithFlags(&evA, cudaEventDisableTiming);
        cudaEventCreateWithFlags(&evB, cudaEventDisableTiming);
    }

    cudaFuncSetAttribute(k_gemm<0>, cudaFuncAttributeMaxDynamicSharedMemorySize, GSMEM);
    cudaFuncSetAttribute(k_gemm<1>, cudaFuncAttributeMaxDynamicSharedMemorySize, GSMEM);

    int gtiles = (N + 63) / 64;

    // prep: zero cnt + dup weights (both branches depend on it)
    k_prep<<<(N + 255) / 256, 256>>>(Ws, Wn, N);

    // fork: self-half GEMM on side stream
    cudaEventRecord(evA, 0);
    cudaStreamWaitEvent(s2, evA, 0);
    k_gemm<0><<<gtiles, 256, GSMEM, s2>>>(embs, bs, bn, out, N);

    // CSR/SpMM chain on default stream
    k_hist<<<(E / 4 + 255) / 256, 256>>>(rows, E);
    k_scan1<<<NB_SCAN, 256>>>(N);
    k_scan3<<<(N + 255) / 256, 256>>>(N, E);
    k_scatter<<<(E / 4 + 255) / 256, 256>>>(rows, cols, vals, E);
    k_spmm<<<(N + 7) / 8, 256>>>((const float4*)embs, N);

    // join, then neighbor-half GEMM fuses add + leaky
    cudaEventRecord(evB, s2);
    cudaStreamWaitEvent(0, evB, 0);
    k_gemm<1><<<gtiles, 256, GSMEM>>>(nullptr, nullptr, nullptr, out, N);
}

// round 16
// speedup vs baseline: 1.0558x; 1.0558x over previous
#include <cuda_runtime.h>
#include <cstdint>

#define N_ENT   100000
#define D       128
#define NB_SCAN 49
#define AST     66                          // dup-A float stride per k (even -> 8B aligned)
#define GSMEM   (65536 + 128 * AST * 4)     // sW 64KB + sA-dup 33.8KB = 99KB -> 2 CTAs/SM

// ---------------- scratch (static, no allocs) ----------------
__device__ float4 g_neigh4[(size_t)N_ENT * 32];
__device__ float  g_WT[256 * 128];          // k-major concat(W_self, W_neigh)
__device__ int    g_cnt[N_ENT];
__device__ int    g_start[N_ENT + 1];
__device__ int    g_head[N_ENT];
__device__ int    g_bsum[64];
__device__ float2 g_edge[1600000];

// ---------------- f32x2 helpers ----------------
__device__ __forceinline__ unsigned long long ffma2(unsigned long long a,
                                                    unsigned long long b,
                                                    unsigned long long c) {
    unsigned long long d;
    asm("fma.rn.f32x2 %0, %1, %2, %3;" : "=l"(d) : "l"(a), "l"(b), "l"(c));
    return d;
}
__device__ __forceinline__ unsigned long long pack2(float x, float y) {
    unsigned long long r;
    asm("mov.b64 %0, {%1, %2};" : "=l"(r) : "f"(x), "f"(y));
    return r;
}
__device__ __forceinline__ void unpack2(unsigned long long v, float& x, float& y) {
    asm("mov.b64 {%0, %1}, %2;" : "=f"(x), "=f"(y) : "l"(v));
}

// ---------------- prep: zero cnt + k-major weight transpose (fused) ----------------
__global__ void k_prep(const float* __restrict__ Ws, const float* __restrict__ Wn, int n) {
    int i = blockIdx.x * blockDim.x + threadIdx.x;
    if (i < n) g_cnt[i] = 0;
    if (i < 256 * 128) {
        int k = i >> 7, o = i & 127;
        g_WT[i] = (k < 128) ? Ws[o * 128 + k] : Wn[o * 128 + (k - 128)];
    }
}

// ---------------- CSR build (r13, unchanged) ----------------
__global__ void k_hist(const int* __restrict__ rows, int E) {
    int i = (blockIdx.x * blockDim.x + threadIdx.x) * 4;
    if (i + 4 <= E) {
        int4 r = *(const int4*)(rows + i);
        atomicAdd(&g_cnt[r.x], 1);
        atomicAdd(&g_cnt[r.y], 1);
        atomicAdd(&g_cnt[r.z], 1);
        atomicAdd(&g_cnt[r.w], 1);
    } else {
        for (; i < E; i++) atomicAdd(&g_cnt[rows[i]], 1);
    }
}
__global__ void k_scan1(int n) {
    __shared__ int ss[256];
    int b = blockIdx.x, t = threadIdx.x;
    int base = b * 2048 + t * 8;
    int loc[8], s = 0;
#pragma unroll
    for (int i = 0; i < 8; i++) {
        int idx = base + i;
        loc[i] = (idx < n) ? g_cnt[idx] : 0;
        s += loc[i];
    }
    ss[t] = s;
    __syncthreads();
    for (int off = 1; off < 256; off <<= 1) {
        int v = 0;
        if (t >= off) v = ss[t - off];
        __syncthreads();
        if (t >= off) ss[t] += v;
        __syncthreads();
    }
    int excl = ss[t] - s;
#pragma unroll
    for (int i = 0; i < 8; i++) {
        int idx = base + i;
        if (idx < n) g_start[idx] = excl;
        excl += loc[i];
    }
    if (t == 255) g_bsum[b] = ss[255];
}
__global__ void k_scan3(int n, int E) {
    __shared__ int soff;
    int bb = blockIdx.x >> 3;
    if (threadIdx.x < 32) {
        int s = 0;
        for (int i = threadIdx.x; i < bb; i += 32) s += g_bsum[i];
#pragma unroll
        for (int o = 16; o; o >>= 1) s += __shfl_down_sync(0xFFFFFFFFu, s, o);
        if (threadIdx.x == 0) soff = s;
    }
    __syncthreads();
    int i = blockIdx.x * 256 + threadIdx.x;
    if (i < n) {
        int v = g_start[i] + soff;
        g_start[i] = v;
        g_head[i] = v;
    }
    if (i == 0) g_start[n] = E;
}
__global__ void k_scatter(const int* __restrict__ rows, const int* __restrict__ cols,
                          const float* __restrict__ vals, int E) {
    int i = (blockIdx.x * blockDim.x + threadIdx.x) * 4;
    if (i + 4 <= E) {
        int4 r = *(const int4*)(rows + i);
        int4 c = *(const int4*)(cols + i);
        float4 v = *(const float4*)(vals + i);
        int p0 = atomicAdd(&g_head[r.x], 1);
        int p1 = atomicAdd(&g_head[r.y], 1);
        int p2 = atomicAdd(&g_head[r.z], 1);
        int p3 = atomicAdd(&g_head[r.w], 1);
        g_edge[p0] = make_float2(__int_as_float(c.x), v.x);
        g_edge[p1] = make_float2(__int_as_float(c.y), v.y);
        g_edge[p2] = make_float2(__int_as_float(c.z), v.z);
        g_edge[p3] = make_float2(__int_as_float(c.w), v.w);
    } else {
        for (; i < E; i++) {
            int pos = atomicAdd(&g_head[rows[i]], 1);
            g_edge[pos] = make_float2(__int_as_float(cols[i]), vals[i]);
        }
    }
}
__global__ void k_spmm(const float4* __restrict__ embs, int n) {
    int w = (int)((blockIdx.x * blockDim.x + threadIdx.x) >> 5);
    int lane = threadIdx.x & 31;
    if (w >= n) return;
    int s = g_start[w], t = g_start[w + 1];
    float4 acc = make_float4(0.f, 0.f, 0.f, 0.f);
    int e = s;
    for (; e + 8 <= t; e += 8) {
        float2 ed[8];
        float4 rr[8];
#pragma unroll
        for (int q = 0; q < 8; q++) ed[q] = g_edge[e + q];
#pragma unroll
        for (int q = 0; q < 8; q++)
            rr[q] = embs[(size_t)__float_as_int(ed[q].x) * 32 + lane];
#pragma unroll
        for (int q = 0; q < 8; q++) {
            acc.x += ed[q].y * rr[q].x;
            acc.y += ed[q].y * rr[q].y;
            acc.z += ed[q].y * rr[q].z;
            acc.w += ed[q].y * rr[q].w;
        }
    }
    for (; e < t; e++) {
        float2 ed = g_edge[e];
        float4 r = embs[(size_t)__float_as_int(ed.x) * 32 + lane];
        acc.x += ed.y * r.x; acc.y += ed.y * r.y;
        acc.z += ed.y * r.z; acc.w += ed.y * r.w;
    }
    g_neigh4[(size_t)w * 32 + lane] = acc;
}

// ---------------- GEMM half: r13 core with dup-A LDS.64 (no dup MOVs) ----------------
// 32-row x 128-col tiles, 128 threads, split-K halves. 2 CTAs/SM (97KB).
// HALF=0: out = x @ Ws^T + (bs + bn)
// HALF=1: out = leaky(out + neigh @ Wn^T)
template <int HALF>
__global__ __launch_bounds__(128)
void k_gemm(const float* __restrict__ A0,
            const float* __restrict__ bs,
            const float* __restrict__ bn,
            float* __restrict__ out, int N) {
    extern __shared__ float sm[];
    float* sW = sm;                 // [128 k][128 c]
    float* sA = sm + 128 * 128;     // [128 k][AST]: dup pairs (v,v) @ 2r; reused as red[32][128]
    const float* src = HALF ? (const float*)g_neigh4 : A0;
    int tid = threadIdx.x;
    int tc = tid & 15;              // col group: cols tc*8 .. tc*8+7
    int tr = (tid >> 4) & 3;        // row group: rows tr*8 .. tr*8+7
    int kh = tid >> 6;              // split-K half: k in [kh*64, kh*64+64)
    int base = blockIdx.x * 32;
    int r0 = tr * 8;

    {   // weights: 64KB coalesced copy of this half's slab
        const float4* wt4 = (const float4*)(g_WT + HALF * 128 * 128);
        float4* sW4 = (float4*)sW;
#pragma unroll
        for (int i = 0; i < 32; i++) sW4[tid + i * 128] = wt4[tid + i * 128];
    }
    // A tile: 32 rows x 128 k, dup pairs; thread = k, loop rows (coalesced LDG)
    for (int it = 0; it < 32; it++) {
        int gr = base + it;
        float v = (gr < N) ? src[(size_t)gr * 128 + tid] : 0.f;
        *(float2*)(sA + tid * AST + 2 * it) = make_float2(v, v);
    }
    __syncthreads();

    unsigned long long acc[8][4];
#pragma unroll
    for (int i = 0; i < 8; i++)
#pragma unroll
        for (int j = 0; j < 4; j++) acc[i][j] = 0ull;

    int k0 = kh * 64;
#pragma unroll 4
    for (int kk = 0; kk < 64; kk++) {
        int k = k0 + kk;
        const float* wr = sW + k * 128 + tc * 8;
        float4 w0 = *(const float4*)wr;
        float4 w1 = *(const float4*)(wr + 4);
        unsigned long long w2[4];
        w2[0] = pack2(w0.x, w0.y); w2[1] = pack2(w0.z, w0.w);
        w2[2] = pack2(w1.x, w1.y); w2[3] = pack2(w1.z, w1.w);
        const float* ar = sA + k * AST + 2 * r0;
#pragma unroll
        for (int i = 0; i < 8; i++) {
            unsigned long long a2 = *(const unsigned long long*)(ar + 2 * i); // (v,v) direct
#pragma unroll
            for (int j = 0; j < 4; j++) acc[i][j] = ffma2(a2, w2[j], acc[i][j]);
        }
    }

    // cross-half reduction through sA region (red = [32][128])
    __syncthreads();
    float* red = sA;
    if (kh == 1) {
#pragma unroll
        for (int i = 0; i < 8; i++) {
            float v[8];
#pragma unroll
            for (int j = 0; j < 4; j++) unpack2(acc[i][j], v[2 * j], v[2 * j + 1]);
            float* rp = red + (r0 + i) * 128 + tc * 8;
            *(float4*)rp = make_float4(v[0], v[1], v[2], v[3]);
            *(float4*)(rp + 4) = make_float4(v[4], v[5], v[6], v[7]);
        }
    }
    __syncthreads();
    if (kh == 0) {
        float bb[8];
        if (!HALF) {
#pragma unroll
            for (int j = 0; j < 8; j++) {
                int c = tc * 8 + j;
                bb[j] = bs[c] + bn[c];
            }
        }
#pragma unroll
        for (int i = 0; i < 8; i++) {
            int gr = base + r0 + i;
            if (gr >= N) continue;
            float v[8];
#pragma unroll
            for (int j = 0; j < 4; j++) unpack2(acc[i][j], v[2 * j], v[2 * j + 1]);
            const float* rp = red + (r0 + i) * 128 + tc * 8;
            float* op = out + (size_t)gr * 128 + tc * 8;
            if (HALF) {
                float4 o0 = *(const float4*)op;
                float4 o1 = *(const float4*)(op + 4);
                float oo[8] = {o0.x, o0.y, o0.z, o0.w, o1.x, o1.y, o1.z, o1.w};
#pragma unroll
                for (int j = 0; j < 8; j++) {
                    float t = v[j] + rp[j] + oo[j];
                    v[j] = t > 0.f ? t : 0.01f * t;
                }
            } else {
#pragma unroll
                for (int j = 0; j < 8; j++) v[j] += rp[j] + bb[j];
            }
            *(float4*)op = make_float4(v[0], v[1], v[2], v[3]);
            *(float4*)(op + 4) = make_float4(v[4], v[5], v[6], v[7]);
        }
    }
}

extern "C" void kernel_launch(void* const* d_in, const int* in_sizes, int n_in,
                              void* d_out, int out_size) {
    const float* embs = (const float*)d_in[0];
    const int*   rows = (const int*)d_in[1];
    const int*   cols = (const int*)d_in[2];
    const float* vals = (const float*)d_in[3];
    const float* Ws   = (const float*)d_in[4];
    const float* bs   = (const float*)d_in[5];
    const float* Wn   = (const float*)d_in[6];
    const float* bn   = (const float*)d_in[7];
    float* out = (float*)d_out;

    int N = in_sizes[0] / D;
    int E = in_sizes[1];

    static cudaStream_t s2 = nullptr;
    static cudaEvent_t evA = nullptr, evB = nullptr;
    if (!s2) {
        cudaStreamCreateWithFlags(&s2, cudaStreamNonBlocking);
        cudaEventCreateWithFlags(&evA, cudaEventDisableTiming);
        cudaEventCreateWithFlags(&evB, cudaEventDisableTiming);
    }

    cudaFuncSetAttribute(k_gemm<0>, cudaFuncAttributeMaxDynamicSharedMemorySize, GSMEM);
    cudaFuncSetAttribute(k_gemm<1>, cudaFuncAttributeMaxDynamicSharedMemorySize, GSMEM);

    int gtiles = (N + 31) / 32;

    // prep: zero cnt + weight transpose (both branches depend on it)
    k_prep<<<(N + 255) / 256, 256>>>(Ws, Wn, N);

    // fork: self-half GEMM on side stream
    cudaEventRecord(evA, 0);
    cudaStreamWaitEvent(s2, evA, 0);
    k_gemm<0><<<gtiles, 128, GSMEM, s2>>>(embs, bs, bn, out, N);

    // CSR/SpMM chain on default stream
    k_hist<<<(E / 4 + 255) / 256, 256>>>(rows, E);
    k_scan1<<<NB_SCAN, 256>>>(N);
    k_scan3<<<(N + 255) / 256, 256>>>(N, E);
    k_scatter<<<(E / 4 + 255) / 256, 256>>>(rows, cols, vals, E);
    k_spmm<<<(N + 7) / 8, 256>>>((const float4*)embs, N);

    // join, then neighbor-half GEMM fuses add + leaky
    cudaEventRecord(evB, s2);
    cudaStreamWaitEvent(0, evB, 0);
    k_gemm<1><<<gtiles, 128, GSMEM>>>(nullptr, nullptr, nullptr, out, N);
}

// round 17
// speedup vs baseline: 1.3393x; 1.2685x over previous
#include <cuda_runtime.h>
#include <cstdint>

#define N_ENT   100000
#define D       128
#define NB_SCAN 49
#define AS      65
#define GSMEM   ((128 * 128 + 128 * AS) * 4)

// ---------------- scratch (static, no allocs) ----------------
__device__ float4 g_neigh4[(size_t)N_ENT * 32];
__device__ float  g_WT[256 * 128];                // k-major concat(W_self, W_neigh)
__device__ int    g_cnt[N_ENT];
__device__ int    g_start[N_ENT + 1];
__device__ int    g_pos[1600000];                 // per-edge rank within its row
__device__ int    g_bsum[64];
__device__ float2 g_edge[1600000];

// ---------------- f32x2 helpers ----------------
__device__ __forceinline__ unsigned long long ffma2(unsigned long long a,
                                                    unsigned long long b,
                                                    unsigned long long c) {
    unsigned long long d;
    asm("fma.rn.f32x2 %0, %1, %2, %3;" : "=l"(d) : "l"(a), "l"(b), "l"(c));
    return d;
}
__device__ __forceinline__ unsigned long long pack2(float x, float y) {
    unsigned long long r;
    asm("mov.b64 %0, {%1, %2};" : "=l"(r) : "f"(x), "f"(y));
    return r;
}
__device__ __forceinline__ void unpack2(unsigned long long v, float& x, float& y) {
    asm("mov.b64 {%0, %1}, %2;" : "=f"(x), "=f"(y) : "l"(v));
}

// ---------------- prep: zero cnt + k-major weight transpose (fused) ----------------
__global__ void k_prep(const float* __restrict__ Ws, const float* __restrict__ Wn, int n) {
    int i = blockIdx.x * blockDim.x + threadIdx.x;
    if (i < n) g_cnt[i] = 0;
    if (i < 256 * 128) {
        int k = i >> 7, o = i & 127;
        g_WT[i] = (k < 128) ? Ws[o * 128 + k] : Wn[o * 128 + (k - 128)];
    }
}

// ---------------- CSR build ----------------
// hist: 4 edges/thread; the returned rank IS the edge's slot within its row
__global__ void k_hist(const int* __restrict__ rows, int E) {
    int i = (blockIdx.x * blockDim.x + threadIdx.x) * 4;
    if (i + 4 <= E) {
        int4 r = *(const int4*)(rows + i);
        int4 p;
        p.x = atomicAdd(&g_cnt[r.x], 1);
        p.y = atomicAdd(&g_cnt[r.y], 1);
        p.z = atomicAdd(&g_cnt[r.z], 1);
        p.w = atomicAdd(&g_cnt[r.w], 1);
        *(int4*)(g_pos + i) = p;
    } else {
        for (; i < E; i++) g_pos[i] = atomicAdd(&g_cnt[rows[i]], 1);
    }
}
__global__ void k_scan1(int n) {
    __shared__ int ss[256];
    int b = blockIdx.x, t = threadIdx.x;
    int base = b * 2048 + t * 8;
    int loc[8], s = 0;
#pragma unroll
    for (int i = 0; i < 8; i++) {
        int idx = base + i;
        loc[i] = (idx < n) ? g_cnt[idx] : 0;
        s += loc[i];
    }
    ss[t] = s;
    __syncthreads();
    for (int off = 1; off < 256; off <<= 1) {
        int v = 0;
        if (t >= off) v = ss[t - off];
        __syncthreads();
        if (t >= off) ss[t] += v;
        __syncthreads();
    }
    int excl = ss[t] - s;
#pragma unroll
    for (int i = 0; i < 8; i++) {
        int idx = base + i;
        if (idx < n) g_start[idx] = excl;
        excl += loc[i];
    }
    if (t == 255) g_bsum[b] = ss[255];
}
__global__ void k_scan3(int n, int E) {
    __shared__ int soff;
    int bb = blockIdx.x >> 3;
    if (threadIdx.x < 32) {
        int s = 0;
        for (int i = threadIdx.x; i < bb; i += 32) s += g_bsum[i];
#pragma unroll
        for (int o = 16; o; o >>= 1) s += __shfl_down_sync(0xFFFFFFFFu, s, o);
        if (threadIdx.x == 0) soff = s;
    }
    __syncthreads();
    int i = blockIdx.x * 256 + threadIdx.x;
    if (i < n) g_start[i] += soff;
    if (i == 0) g_start[n] = E;
}
// scatter: atomic-free — slot = g_start[row] + precomputed rank
__global__ void k_scatter(const int* __restrict__ rows, const int* __restrict__ cols,
                          const float* __restrict__ vals, int E) {
    int i = (blockIdx.x * blockDim.x + threadIdx.x) * 4;
    if (i + 4 <= E) {
        int4 r = *(const int4*)(rows + i);
        int4 c = *(const int4*)(cols + i);
        float4 v = *(const float4*)(vals + i);
        int4 p = *(const int4*)(g_pos + i);
        g_edge[g_start[r.x] + p.x] = make_float2(__int_as_float(c.x), v.x);
        g_edge[g_start[r.y] + p.y] = make_float2(__int_as_float(c.y), v.y);
        g_edge[g_start[r.z] + p.z] = make_float2(__int_as_float(c.z), v.z);
        g_edge[g_start[r.w] + p.w] = make_float2(__int_as_float(c.w), v.w);
    } else {
        for (; i < E; i++)
            g_edge[g_start[rows[i]] + g_pos[i]] =
                make_float2(__int_as_float(cols[i]), vals[i]);
    }
}
__global__ void k_spmm(const float4* __restrict__ embs, int n) {
    int w = (int)((blockIdx.x * blockDim.x + threadIdx.x) >> 5);
    int lane = threadIdx.x & 31;
    if (w >= n) return;
    int s = g_start[w], t = g_start[w + 1];
    float4 acc = make_float4(0.f, 0.f, 0.f, 0.f);
    int e = s;
    for (; e + 8 <= t; e += 8) {
        float2 ed[8];
        float4 rr[8];
#pragma unroll
        for (int q = 0; q < 8; q++) ed[q] = g_edge[e + q];
#pragma unroll
        for (int q = 0; q < 8; q++)
            rr[q] = embs[(size_t)__float_as_int(ed[q].x) * 32 + lane];
#pragma unroll
        for (int q = 0; q < 8; q++) {
            acc.x += ed[q].y * rr[q].x;
            acc.y += ed[q].y * rr[q].y;
            acc.z += ed[q].y * rr[q].z;
            acc.w += ed[q].y * rr[q].w;
        }
    }
    for (; e < t; e++) {
        float2 ed = g_edge[e];
        float4 r = embs[(size_t)__float_as_int(ed.x) * 32 + lane];
        acc.x += ed.y * r.x; acc.y += ed.y * r.y;
        acc.z += ed.y * r.z; acc.w += ed.y * r.w;
    }
    g_neigh4[(size_t)w * 32 + lane] = acc;
}

// ---------------- GEMM half (r13 core, frozen) ----------------
// HALF=0: out = x @ Ws^T + (bs + bn)
// HALF=1: out = leaky(out + neigh @ Wn^T)
template <int HALF>
__global__ __launch_bounds__(256)
void k_gemm(const float* __restrict__ A0,
            const float* __restrict__ bs,
            const float* __restrict__ bn,
            float* __restrict__ out, int N) {
    extern __shared__ float sm[];
    float* sW = sm;                 // [128 k][128 c]
    float* sA = sm + 128 * 128;     // [128 k][AS]; reused as red[64][128]
    const float* src = HALF ? (const float*)g_neigh4 : A0;
    int tid = threadIdx.x;
    int tc = tid & 15;
    int tr = (tid >> 4) & 7;
    int kh = tid >> 7;
    int base = blockIdx.x * 64;

    {
        const float4* wt4 = (const float4*)(g_WT + HALF * 128 * 128);
        float4* sW4 = (float4*)sW;
#pragma unroll
        for (int i = 0; i < 16; i++) sW4[tid + i * 256] = wt4[tid + i * 256];
    }
    for (int it = 0; it < 32; it++) {
        int r = it * 2 + (tid >> 7);
        int k = tid & 127;
        int gr = base + r;
        float v = (gr < N) ? src[(size_t)gr * 128 + k] : 0.f;
        sA[k * AS + r] = v;
    }
    __syncthreads();

    unsigned long long acc[8][4];
#pragma unroll
    for (int i = 0; i < 8; i++)
#pragma unroll
        for (int j = 0; j < 4; j++) acc[i][j] = 0ull;

    int k0 = kh * 64;
#pragma unroll 4
    for (int kk = 0; kk < 64; kk++) {
        int k = k0 + kk;
        const float* wr = sW + k * 128 + tc * 8;
        float4 w0 = *(const float4*)wr;
        float4 w1 = *(const float4*)(wr + 4);
        unsigned long long w2[4];
        w2[0] = pack2(w0.x, w0.y); w2[1] = pack2(w0.z, w0.w);
        w2[2] = pack2(w1.x, w1.y); w2[3] = pack2(w1.z, w1.w);
        const float* ar = sA + k * AS + tr * 8;
#pragma unroll
        for (int i = 0; i < 8; i++) {
            float av = ar[i];
            unsigned long long a2 = pack2(av, av);
#pragma unroll
            for (int j = 0; j < 4; j++) acc[i][j] = ffma2(a2, w2[j], acc[i][j]);
        }
    }

    __syncthreads();
    float* red = sA;
    if (kh == 1) {
#pragma unroll
        for (int i = 0; i < 8; i++) {
            float v[8];
#pragma unroll
            for (int j = 0; j < 4; j++) unpack2(acc[i][j], v[2 * j], v[2 * j + 1]);
            float* rp = red + (tr * 8 + i) * 128 + tc * 8;
            *(float4*)rp = make_float4(v[0], v[1], v[2], v[3]);
            *(float4*)(rp + 4) = make_float4(v[4], v[5], v[6], v[7]);
        }
    }
    __syncthreads();
    if (kh == 0) {
        float bb[8];
        if (!HALF) {
#pragma unroll
            for (int j = 0; j < 8; j++) {
                int c = tc * 8 + j;
                bb[j] = bs[c] + bn[c];
            }
        }
#pragma unroll
        for (int i = 0; i < 8; i++) {
            int gr = base + tr * 8 + i;
            if (gr >= N) continue;
            float v[8];
#pragma unroll
            for (int j = 0; j < 4; j++) unpack2(acc[i][j], v[2 * j], v[2 * j + 1]);
            const float* rp = red + (tr * 8 + i) * 128 + tc * 8;
            float* op = out + (size_t)gr * 128 + tc * 8;
            if (HALF) {
                float4 o0 = *(const float4*)op;
                float4 o1 = *(const float4*)(op + 4);
                float oo[8] = {o0.x, o0.y, o0.z, o0.w, o1.x, o1.y, o1.z, o1.w};
#pragma unroll
                for (int j = 0; j < 8; j++) {
                    float t = v[j] + rp[j] + oo[j];
                    v[j] = t > 0.f ? t : 0.01f * t;
                }
            } else {
#pragma unroll
                for (int j = 0; j < 8; j++) v[j] += rp[j] + bb[j];
            }
            *(float4*)op = make_float4(v[0], v[1], v[2], v[3]);
            *(float4*)(op + 4) = make_float4(v[4], v[5], v[6], v[7]);
        }
    }
}

extern "C" void kernel_launch(void* const* d_in, const int* in_sizes, int n_in,
                              void* d_out, int out_size) {
    const float* embs = (const float*)d_in[0];
    const int*   rows = (const int*)d_in[1];
    const int*   cols = (const int*)d_in[2];
    const float* vals = (const float*)d_in[3];
    const float* Ws   = (const float*)d_in[4];
    const float* bs   = (const float*)d_in[5];
    const float* Wn   = (const float*)d_in[6];
    const float* bn   = (const float*)d_in[7];
    float* out = (float*)d_out;

    int N = in_sizes[0] / D;
    int E = in_sizes[1];

    static cudaStream_t s2 = nullptr;
    static cudaEvent_t evA = nullptr, evB = nullptr;
    if (!s2) {
        cudaStreamCreateWithFlags(&s2, cudaStreamNonBlocking);
        cudaEventCreateWithFlags(&evA, cudaEventDisableTiming);
        cudaEventCreateWithFlags(&evB, cudaEventDisableTiming);
    }

    cudaFuncSetAttribute(k_gemm<0>, cudaFuncAttributeMaxDynamicSharedMemorySize, GSMEM);
    cudaFuncSetAttribute(k_gemm<1>, cudaFuncAttributeMaxDynamicSharedMemorySize, GSMEM);

    int gtiles = (N + 63) / 64;

    // prep: zero cnt + weight transpose (both branches depend on it)
    k_prep<<<(N + 255) / 256, 256>>>(Ws, Wn, N);

    // fork: self-half GEMM on side stream
    cudaEventRecord(evA, 0);
    cudaStreamWaitEvent(s2, evA, 0);
    k_gemm<0><<<gtiles, 256, GSMEM, s2>>>(embs, bs, bn, out, N);

    // CSR/SpMM chain on default stream
    k_hist<<<(E / 4 + 255) / 256, 256>>>(rows, E);
    k_scan1<<<NB_SCAN, 256>>>(N);
    k_scan3<<<(N + 255) / 256, 256>>>(N, E);
    k_scatter<<<(E / 4 + 255) / 256, 256>>>(rows, cols, vals, E);
    k_spmm<<<(N + 7) / 8, 256>>>((const float4*)embs, N);

    // join, then neighbor-half GEMM fuses add + leaky
    cudaEventRecord(evB, s2);
    cudaStreamWaitEvent(0, evB, 0);
    k_gemm<1><<<gtiles, 256, GSMEM>>>(nullptr, nullptr, nullptr, out, N);
}